// round 2
// baseline (speedup 1.0000x reference)
#include <cuda_runtime.h>
#include <math.h>

// ---------------- problem constants ----------------
#define BB   4
#define NN   1024
#define KNB  32
#define CS   384
#define CZ   128
#define CH   16
#define HH   12
#define PQn  4
#define PVn  8
#define NODES (BB*NN)        // 4096
#define PROJ  1152           // q(192)+k(192)+v(192)+qpts(144)+kvpts(432)
#define EDGES (NODES*KNB)    // 131072
#define EOC   44             // b_bias(12) + pair(32)
#define EOCP  48             // padded
#define CVC   960            // o(192)+o_pt(288)+dists(96)+o_pair(384)
#define COUT  384

// ---------------- scratch (device globals; no allocation) ----------------
__device__ float g_wcat[CS*PROJ];
__device__ float g_proj[NODES*PROJ];
__device__ float g_stat[NODES*2];
__device__ float g_wz  [CZ*EOC];
__device__ float g_eo  [EDGES*EOC];
__device__ float g_cvec[NODES*CVC];

// ---------------- packed fp32x2 helpers ----------------
__device__ __forceinline__ void ffma2(unsigned long long& acc,
                                      unsigned long long a2,
                                      unsigned long long b2) {
    asm("fma.rn.f32x2 %0, %1, %2, %0;" : "+l"(acc) : "l"(a2), "l"(b2));
}
__device__ __forceinline__ unsigned long long pack2(float lo, float hi) {
    unsigned long long r;
    asm("mov.b64 %0, {%1, %2};" : "=l"(r) : "f"(lo), "f"(hi));
    return r;
}
__device__ __forceinline__ void unpack2(unsigned long long v, float& lo, float& hi) {
    asm("mov.b64 {%0, %1}, %2;" : "=f"(lo), "=f"(hi) : "l"(v));
}

// ---------------- weight packing ----------------
__global__ void pack_wcat(const float* __restrict__ wq, const float* __restrict__ wk,
                          const float* __restrict__ wv, const float* __restrict__ wqp,
                          const float* __restrict__ wkv) {
    int idx = blockIdx.x * 256 + threadIdx.x;
    if (idx >= CS * PROJ) return;
    int i = idx / PROJ, j = idx % PROJ;
    float v;
    if      (j < 192) v = wq [i*192 + j];
    else if (j < 384) v = wk [i*192 + j - 192];
    else if (j < 576) v = wv [i*192 + j - 384];
    else if (j < 720) v = wqp[i*144 + j - 576];
    else              v = wkv[i*432 + j - 720];
    g_wcat[idx] = v;
}

__global__ void pack_wz(const float* __restrict__ wb, const float* __restrict__ wdz) {
    int idx = blockIdx.x * 256 + threadIdx.x;
    if (idx >= CZ * EOC) return;
    int i = idx / EOC, j = idx % EOC;
    g_wz[idx] = (j < 12) ? wb[i*12 + j] : wdz[i*32 + j - 12];
}

// ---------------- s row stats (warp per node) ----------------
__global__ __launch_bounds__(256) void k_stat_s(const float* __restrict__ s) {
    int node = blockIdx.x * 8 + (threadIdx.x >> 5);
    int lane = threadIdx.x & 31;
    const float* x = s + (size_t)node * CS;
    float sum = 0.f, ssq = 0.f;
    #pragma unroll
    for (int i = 0; i < 3; i++) {
        float4 v = *(const float4*)(x + lane * 4 + i * 128);
        sum += v.x + v.y + v.z + v.w;
        ssq += v.x*v.x + v.y*v.y + v.z*v.z + v.w*v.w;
    }
    #pragma unroll
    for (int o = 16; o; o >>= 1) {
        sum += __shfl_xor_sync(0xffffffffu, sum, o);
        ssq += __shfl_xor_sync(0xffffffffu, ssq, o);
    }
    if (lane == 0) {
        float mean = sum * (1.0f / CS);
        float var  = ssq * (1.0f / CS) - mean * mean;
        g_stat[node*2    ] = mean;
        g_stat[node*2 + 1] = rsqrtf(var + 1e-5f);
    }
}

// ---------------- GEMM with fp32x2 FMA, optional LN fused into A loads ----
// C[MxN] = LN(A)[MxK] @ B[KxN].  256 threads. Accumulator pairs along M.
template<int BMt, int BNt, int TM, int TN, bool LN>
__global__ __launch_bounds__(256) void gemm2x(const float* __restrict__ A,
                                              const float* __restrict__ B,
                                              float* __restrict__ C,
                                              int Kd, int Nd,
                                              const float* __restrict__ stat,
                                              const float* __restrict__ gam,
                                              const float* __restrict__ bet) {
    __shared__ float As[16][BMt + 4];     // [k][m], row stride multiple of 16B
    __shared__ float Bs[16][BNt];
    constexpr int NTX = BNt / TN;         // 16
    int tid = threadIdx.x;
    int tx = tid % NTX, ty = tid / NTX;
    int m0 = blockIdx.x * BMt, n0 = blockIdx.y * BNt;

    unsigned long long acc[TM/2][TN];
    #pragma unroll
    for (int i = 0; i < TM/2; i++)
        #pragma unroll
        for (int j = 0; j < TN; j++) acc[i][j] = 0ULL;

    constexpr int ALOADS = BMt * 16 / (256 * 4);
    constexpr int BLOADS = BNt * 16 / (256 * 4);

    for (int k0 = 0; k0 < Kd; k0 += 16) {
        #pragma unroll
        for (int t = 0; t < ALOADS; t++) {
            int flat = (tid + t * 256) * 4;
            int row  = flat >> 4;
            int col  = flat & 15;
            float4 v = *(const float4*)(A + (size_t)(m0 + row) * Kd + k0 + col);
            if (LN) {
                float mean = stat[(m0 + row) * 2];
                float rstd = stat[(m0 + row) * 2 + 1];
                v.x = (v.x - mean) * rstd * __ldg(gam + k0 + col + 0) + __ldg(bet + k0 + col + 0);
                v.y = (v.y - mean) * rstd * __ldg(gam + k0 + col + 1) + __ldg(bet + k0 + col + 1);
                v.z = (v.z - mean) * rstd * __ldg(gam + k0 + col + 2) + __ldg(bet + k0 + col + 2);
                v.w = (v.w - mean) * rstd * __ldg(gam + k0 + col + 3) + __ldg(bet + k0 + col + 3);
            }
            As[col + 0][row] = v.x;
            As[col + 1][row] = v.y;
            As[col + 2][row] = v.z;
            As[col + 3][row] = v.w;
        }
        #pragma unroll
        for (int t = 0; t < BLOADS; t++) {
            int flat = (tid + t * 256) * 4;
            int row  = flat / BNt;
            int col  = flat % BNt;
            *(float4*)&Bs[row][col] =
                *(const float4*)(B + (size_t)(k0 + row) * Nd + n0 + col);
        }
        __syncthreads();
        #pragma unroll
        for (int kk = 0; kk < 16; kk++) {
            const unsigned long long* ap = (const unsigned long long*)&As[kk][ty * TM];
            unsigned long long a2[TM/2];
            #pragma unroll
            for (int i = 0; i < TM/2; i++) a2[i] = ap[i];
            float bv[TN];
            #pragma unroll
            for (int j = 0; j < TN; j += 4) {
                float4 b4 = *(float4*)&Bs[kk][tx * TN + j];
                bv[j+0] = b4.x; bv[j+1] = b4.y; bv[j+2] = b4.z; bv[j+3] = b4.w;
            }
            #pragma unroll
            for (int j = 0; j < TN; j++) {
                unsigned long long b2 = pack2(bv[j], bv[j]);
                #pragma unroll
                for (int i = 0; i < TM/2; i++) ffma2(acc[i][j], a2[i], b2);
            }
        }
        __syncthreads();
    }
    float outv[TM][TN];
    #pragma unroll
    for (int i = 0; i < TM/2; i++)
        #pragma unroll
        for (int j = 0; j < TN; j++)
            unpack2(acc[i][j], outv[2*i][j], outv[2*i+1][j]);
    #pragma unroll
    for (int i = 0; i < TM; i++) {
        float* cp = C + (size_t)(m0 + ty * TM + i) * Nd + n0 + tx * TN;
        #pragma unroll
        for (int j = 0; j < TN; j += 4) {
            float4 o = {outv[i][j], outv[i][j+1], outv[i][j+2], outv[i][j+3]};
            *(float4*)(cp + j) = o;
        }
    }
}

// ---------------- z GEMM: LN-fused (stats computed in-block) ---------------
// (131072 x 128) @ (128 x 44->48).  Block: 128 edge rows. 256 threads.
extern __shared__ float zsm[];
__global__ __launch_bounds__(256) void k_zgemm(const float* __restrict__ z,
                                               const float* __restrict__ zsc,
                                               const float* __restrict__ zbi) {
    float* Zt      = zsm;                     // [128 k][132]
    float* Ws      = zsm + 128 * 132;         // [128 k][48]
    float* mean_sh = Ws  + 128 * EOCP;        // [128]
    float* rstd_sh = mean_sh + 128;           // [128]
    int tid = threadIdx.x;
    int r0  = blockIdx.x * 128;

    // weights (padded to 48 cols)
    for (int i = tid; i < CZ * EOCP; i += 256) {
        int row = i / EOCP, col = i % EOCP;
        Ws[i] = (col < EOC) ? g_wz[row * EOC + col] : 0.f;
    }
    // raw z tile, transposed into Zt[k][row]
    #pragma unroll
    for (int t = 0; t < 16; t++) {
        int flat = (tid + t * 256) * 4;
        int row  = flat >> 7;
        int col  = flat & 127;
        float4 v = *(const float4*)(z + (size_t)(r0 + row) * CZ + col);
        Zt[(col + 0) * 132 + row] = v.x;
        Zt[(col + 1) * 132 + row] = v.y;
        Zt[(col + 2) * 132 + row] = v.z;
        Zt[(col + 3) * 132 + row] = v.w;
    }
    __syncthreads();

    // per-row stats (warp w handles rows w*16..w*16+15)
    {
        int w = tid >> 5, lane = tid & 31;
        for (int rr = 0; rr < 16; rr++) {
            int row = w * 16 + rr;
            float s1 = 0.f, s2 = 0.f;
            #pragma unroll
            for (int c = 0; c < 4; c++) {
                float v = Zt[(lane + c * 32) * 132 + row];
                s1 += v; s2 += v * v;
            }
            #pragma unroll
            for (int o = 16; o; o >>= 1) {
                s1 += __shfl_xor_sync(0xffffffffu, s1, o);
                s2 += __shfl_xor_sync(0xffffffffu, s2, o);
            }
            if (lane == 0) {
                float mean = s1 * (1.0f / CZ);
                float var  = s2 * (1.0f / CZ) - mean * mean;
                mean_sh[row] = mean;
                rstd_sh[row] = rsqrtf(var + 1e-5f);
            }
        }
    }
    __syncthreads();

    // apply LN in place (each thread rewrites exactly what it loaded)
    #pragma unroll
    for (int t = 0; t < 16; t++) {
        int flat = (tid + t * 256) * 4;
        int row  = flat >> 7;
        int col  = flat & 127;
        float mean = mean_sh[row], rstd = rstd_sh[row];
        #pragma unroll
        for (int i = 0; i < 4; i++) {
            float v = Zt[(col + i) * 132 + row];
            Zt[(col + i) * 132 + row] =
                (v - mean) * rstd * __ldg(zsc + col + i) + __ldg(zbi + col + i);
        }
    }
    __syncthreads();

    // compute: ty 0..31 -> 4 rows, tx 0..7 -> 6 cols
    int tx = tid & 7, ty = tid >> 3;
    unsigned long long acc0[6], acc1[6];
    #pragma unroll
    for (int j = 0; j < 6; j++) { acc0[j] = 0ULL; acc1[j] = 0ULL; }
    #pragma unroll 4
    for (int kk = 0; kk < CZ; kk++) {
        const unsigned long long* ap =
            (const unsigned long long*)&Zt[kk * 132 + ty * 4];
        unsigned long long a01 = ap[0], a23 = ap[1];
        const float* wp = &Ws[kk * EOCP + tx * 6];
        #pragma unroll
        for (int j = 0; j < 6; j++) {
            unsigned long long b2 = pack2(wp[j], wp[j]);
            ffma2(acc0[j], a01, b2);
            ffma2(acc1[j], a23, b2);
        }
    }
    #pragma unroll
    for (int j = 0; j < 6; j++) {
        int col = tx * 6 + j;
        if (col < EOC) {
            float v0, v1, v2, v3;
            unpack2(acc0[j], v0, v1);
            unpack2(acc1[j], v2, v3);
            size_t base = (size_t)(r0 + ty * 4) * EOC + col;
            g_eo[base          ] = v0;
            g_eo[base + EOC    ] = v1;
            g_eo[base + 2*EOC  ] = v2;
            g_eo[base + 3*EOC  ] = v3;
        }
    }
}

// ---------------- attention: one block (128 thr) per node ----------------
// rot/trans cancel algebraically (orthonormal rot, softmax sums to 1).
__global__ __launch_bounds__(128) void k_attn(const int*   __restrict__ edge_index,
                                              const float* __restrict__ s_mask,
                                              const float* __restrict__ head_w) {
    int node = blockIdx.x;
    int tid  = threadIdx.x;
    int b    = node >> 10;

    __shared__ int   nbroff_sh[KNB];
    __shared__ float msk_sh[KNB];
    __shared__ float q_sh[HH * CH];
    __shared__ float qp_sh[HH * PQn * 3];
    __shared__ float a_sh[HH][KNB];
    __shared__ float opt_sh[HH * PVn * 3];
    __shared__ float hw_sh[HH];

    if (tid < KNB) {
        int idx = edge_index[(size_t)node * KNB + tid];
        nbroff_sh[tid] = (b * NN + idx) * PROJ;
        msk_sh[tid]    = s_mask[node] * s_mask[b * NN + idx];
    }
    for (int i = tid; i < HH * CH; i += 128)
        q_sh[i] = g_proj[(size_t)node * PROJ + i];
    for (int i = tid; i < HH * PQn * 3; i += 128)
        qp_sh[i] = g_proj[(size_t)node * PROJ + 576 + i];
    if (tid < HH)
        hw_sh[tid] = log1pf(__expf(head_w[tid])) * 0.13608276348795434f;
    __syncthreads();

    int lane = tid & 31, warp = tid >> 5;
    int no   = nbroff_sh[lane];
    float mk = msk_sh[lane];
    const float* kr = g_proj + no;

    #pragma unroll
    for (int hi = 0; hi < 3; hi++) {
        int h = warp * 3 + hi;
        const float4* q4 = (const float4*)(q_sh + h * CH);
        const float4* k4 = (const float4*)(kr + 192 + h * CH);
        float dot = 0.f;
        #pragma unroll
        for (int c = 0; c < 4; c++) {
            float4 qa = q4[c], kb = k4[c];
            dot += qa.x*kb.x + qa.y*kb.y + qa.z*kb.z + qa.w*kb.w;
        }
        float sq = 0.f;
        const float* qp = qp_sh + h * 12;
        const float* kp = kr + 720 + h * 36;
        #pragma unroll
        for (int j = 0; j < 12; j++) {
            float d = qp[j] - kp[j];
            sq += d * d;
        }
        float bias  = g_eo[(size_t)(node * KNB + lane) * EOC + h];
        float logit = dot * 0.14433756729740643f
                    + bias * 0.5773502691896258f
                    - 0.5f * hw_sh[h] * sq
                    + 100000.0f * (mk - 1.0f);
        float mx = logit;
        #pragma unroll
        for (int o = 16; o; o >>= 1) mx = fmaxf(mx, __shfl_xor_sync(0xffffffffu, mx, o));
        float e = __expf(logit - mx);
        float sm = e;
        #pragma unroll
        for (int o = 16; o; o >>= 1) sm += __shfl_xor_sync(0xffffffffu, sm, o);
        a_sh[h][lane] = e / sm;
    }
    __syncthreads();

    float* cv = g_cvec + (size_t)node * CVC;
    for (int oi = tid; oi < CVC; oi += 128) {
        float acc = 0.f;
        if (oi < 192) {
            int h = oi >> 4;
            int off = 384 + oi;
            #pragma unroll 8
            for (int k = 0; k < KNB; k++)
                acc += a_sh[h][k] * g_proj[nbroff_sh[k] + off];
            cv[oi] = acc;
        } else if (oi < 480) {
            int j = oi - 192;
            int h = j / 24, r = j % 24;
            int off = 720 + h * 36 + 12 + r;
            #pragma unroll 8
            for (int k = 0; k < KNB; k++)
                acc += a_sh[h][k] * g_proj[nbroff_sh[k] + off];
            opt_sh[j] = acc;
            cv[oi] = acc;
        } else if (oi >= 576) {
            int j = oi - 576;
            int h = j >> 5, c = j & 31;
            const float* eb = g_eo + (size_t)(node * KNB) * EOC + 12 + c;
            #pragma unroll 8
            for (int k = 0; k < KNB; k++)
                acc += a_sh[h][k] * eb[(size_t)k * EOC];
            cv[oi] = acc;
        }
    }
    __syncthreads();
    if (tid < HH * PVn) {
        float x = opt_sh[tid*3], y = opt_sh[tid*3+1], zz = opt_sh[tid*3+2];
        cv[480 + tid] = sqrtf(x*x + y*y + zz*zz + 1e-8f);
    }
}

// ---------------- launch ----------------
extern "C" void kernel_launch(void* const* d_in, const int* in_sizes, int n_in,
                              void* d_out, int out_size) {
    const float* s           = (const float*)d_in[0];
    const float* z           = (const float*)d_in[1];
    const int*   edge_index  = (const int*)  d_in[2];
    // d_in[3] rot, d_in[4] trans: cancel algebraically -> unused
    const float* s_mask      = (const float*)d_in[5];
    const float* ln_s_scale  = (const float*)d_in[6];
    const float* ln_s_bias   = (const float*)d_in[7];
    const float* ln_z_scale  = (const float*)d_in[8];
    const float* ln_z_bias   = (const float*)d_in[9];
    const float* w_q         = (const float*)d_in[10];
    const float* w_k         = (const float*)d_in[11];
    const float* w_v         = (const float*)d_in[12];
    const float* w_q_pts     = (const float*)d_in[13];
    const float* w_kv_pts    = (const float*)d_in[14];
    const float* w_b         = (const float*)d_in[15];
    const float* w_down_z    = (const float*)d_in[16];
    const float* head_weights= (const float*)d_in[17];
    const float* w_out       = (const float*)d_in[18];
    float* out = (float*)d_out;

    const int zgemm_smem = (128 * 132 + 128 * EOCP + 256) * sizeof(float);
    cudaFuncSetAttribute(k_zgemm, cudaFuncAttributeMaxDynamicSharedMemorySize, zgemm_smem);

    void *p_wcat, *p_proj, *p_stat, *p_cvec;
    cudaGetSymbolAddress(&p_wcat, g_wcat);
    cudaGetSymbolAddress(&p_proj, g_proj);
    cudaGetSymbolAddress(&p_stat, g_stat);
    cudaGetSymbolAddress(&p_cvec, g_cvec);

    pack_wcat<<<(CS * PROJ + 255) / 256, 256>>>(w_q, w_k, w_v, w_q_pts, w_kv_pts);
    pack_wz  <<<(CZ * EOC  + 255) / 256, 256>>>(w_b, w_down_z);
    k_stat_s <<<NODES / 8, 256>>>(s);

    // GEMM1: LN(s) @ wcat -> proj   (4096x384)@(384x1152)
    gemm2x<128, 128, 8, 8, true><<<dim3(NODES/128, PROJ/128), 256>>>(
        s, (const float*)p_wcat, (float*)p_proj, CS, PROJ,
        (const float*)p_stat, ln_s_scale, ln_s_bias);

    // zGEMM (stats + LN fused)
    k_zgemm<<<EDGES / 128, 256, zgemm_smem>>>(z, ln_z_scale, ln_z_bias);

    k_attn<<<NODES, 128>>>(edge_index, s_mask, head_weights);

    // GEMM2: cvec @ w_out -> out    (4096x960)@(960x384)
    gemm2x<64, 128, 4, 8, false><<<dim3(NODES/64, COUT/128), 256>>>(
        (const float*)p_cvec, w_out, out, CVC, COUT,
        nullptr, nullptr, nullptr);
}

// round 4
// speedup vs baseline: 1.5688x; 1.5688x over previous
#include <cuda_runtime.h>
#include <cuda_bf16.h>
#include <math.h>
#include <stdint.h>

// ---------------- problem constants ----------------
#define BB   4
#define NN   1024
#define KNB  32
#define CS   384
#define CZ   128
#define CH   16
#define HH   12
#define PQn  4
#define PVn  8
#define NODES (BB*NN)        // 4096
#define PROJ  1152           // q(192)+k(192)+v(192)+qpts(144)+kvpts(432)
#define EDGES (NODES*KNB)    // 131072
#define EOC   44             // b_bias(12) + pair(32)
#define CVC   960            // o(192)+o_pt(288)+dists(96)+o_pair(384)
#define COUT  384

// ---------------- scratch (device globals; no allocation) ----------------
__device__ float g_wcat[CS*PROJ];
__device__ float g_proj[NODES*PROJ];
__device__ float g_stat[NODES*2];
__device__ float g_zstat[EDGES*2];
__device__ float g_wz  [CZ*EOC];
__device__ float g_eo  [EDGES*EOC];
__device__ float g_cvec[NODES*CVC];

// ---------------- helpers ----------------
__device__ __forceinline__ uint32_t smem_u32(const void* p) {
    uint32_t a;
    asm("{ .reg .u64 t; cvta.to.shared.u64 t, %1; cvt.u32.u64 %0, t; }"
        : "=r"(a) : "l"(p));
    return a;
}
__device__ __forceinline__ void cvt_hilo(float x, __nv_bfloat16& h, __nv_bfloat16& l) {
    h = __float2bfloat16(x);
    l = __float2bfloat16(x - __bfloat162float(h));
}
__device__ __forceinline__ void ldsm4(uint32_t& r0, uint32_t& r1, uint32_t& r2,
                                      uint32_t& r3, uint32_t addr) {
    asm volatile("ldmatrix.sync.aligned.m8n8.x4.shared.b16 {%0,%1,%2,%3}, [%4];"
                 : "=r"(r0), "=r"(r1), "=r"(r2), "=r"(r3) : "r"(addr));
}
__device__ __forceinline__ void ldsm4t(uint32_t& r0, uint32_t& r1, uint32_t& r2,
                                       uint32_t& r3, uint32_t addr) {
    asm volatile("ldmatrix.sync.aligned.m8n8.x4.trans.shared.b16 {%0,%1,%2,%3}, [%4];"
                 : "=r"(r0), "=r"(r1), "=r"(r2), "=r"(r3) : "r"(addr));
}
__device__ __forceinline__ void mma16816(float* c, const uint32_t* a, const uint32_t* b) {
    asm volatile(
        "mma.sync.aligned.m16n8k16.row.col.f32.bf16.bf16.f32 "
        "{%0,%1,%2,%3}, {%4,%5,%6,%7}, {%8,%9}, {%0,%1,%2,%3};"
        : "+f"(c[0]), "+f"(c[1]), "+f"(c[2]), "+f"(c[3])
        : "r"(a[0]), "r"(a[1]), "r"(a[2]), "r"(a[3]), "r"(b[0]), "r"(b[1]));
}

// ================= weight packing ==========================
__global__ void pack_wcat(const float* __restrict__ wq, const float* __restrict__ wk,
                          const float* __restrict__ wv, const float* __restrict__ wqp,
                          const float* __restrict__ wkv) {
    int idx = blockIdx.x * 256 + threadIdx.x;
    if (idx >= CS * PROJ) return;
    int i = idx / PROJ, j = idx % PROJ;
    float v;
    if      (j < 192) v = wq [i*192 + j];
    else if (j < 384) v = wk [i*192 + j - 192];
    else if (j < 576) v = wv [i*192 + j - 384];
    else if (j < 720) v = wqp[i*144 + j - 576];
    else              v = wkv[i*432 + j - 720];
    g_wcat[idx] = v;
}

__global__ void pack_wz(const float* __restrict__ wb, const float* __restrict__ wdz) {
    int idx = blockIdx.x * 256 + threadIdx.x;
    if (idx >= CZ * EOC) return;
    int i = idx / EOC, j = idx % EOC;
    g_wz[idx] = (j < 12) ? wb[i*12 + j] : wdz[i*32 + j - 12];
}

// ---------------- s row stats (warp per node) ----------------
__global__ __launch_bounds__(256) void k_stat_s(const float* __restrict__ s) {
    int node = blockIdx.x * 8 + (threadIdx.x >> 5);
    int lane = threadIdx.x & 31;
    const float* x = s + (size_t)node * CS;
    float sum = 0.f, ssq = 0.f;
    #pragma unroll
    for (int i = 0; i < 3; i++) {
        float4 v = *(const float4*)(x + lane * 4 + i * 128);
        sum += v.x + v.y + v.z + v.w;
        ssq += v.x*v.x + v.y*v.y + v.z*v.z + v.w*v.w;
    }
    #pragma unroll
    for (int o = 16; o; o >>= 1) {
        sum += __shfl_xor_sync(0xffffffffu, sum, o);
        ssq += __shfl_xor_sync(0xffffffffu, ssq, o);
    }
    if (lane == 0) {
        float mean = sum * (1.0f / CS);
        float var  = ssq * (1.0f / CS) - mean * mean;
        g_stat[node*2    ] = mean;
        g_stat[node*2 + 1] = rsqrtf(var + 1e-5f);
    }
}

// ================= bf16x3 tensor-core GEMM via mma.sync ====================
// C[M x Nd] = (opt LN)(A)[M x Kd] @ B[Kd x Nd].  CTA tile 128x128, 8 warps
// (2 M x 4 N), warp tile 64x32 = 4x4 m16n8k16 fragments. K chunks of 32 fp32
// split into bf16 hi/lo; three passes hh + lh + hl.
#define AST 40     // A smem row stride in bf16 (conflict-free for ldmatrix)
#define BST 136    // B smem row stride in bf16

template<bool LN>
__global__ __launch_bounds__(256) void tgemm(const float* __restrict__ A,
                                             const float* __restrict__ B,
                                             float* __restrict__ C,
                                             int Kd, int Nd, int nk,
                                             const float* __restrict__ stat,
                                             const float* __restrict__ gam,
                                             const float* __restrict__ bet) {
    __shared__ __nv_bfloat16 Ah[128 * AST];
    __shared__ __nv_bfloat16 Al[128 * AST];
    __shared__ __nv_bfloat16 Bh[32 * BST];
    __shared__ __nv_bfloat16 Bl[32 * BST];

    int tid = threadIdx.x, wid = tid >> 5, lane = tid & 31;
    int m0 = blockIdx.x * 128, n0 = blockIdx.y * 128;
    int wm = (wid >> 2) * 64;          // warp M offset in tile
    int wn = (wid & 3) * 32;           // warp N offset in tile

    float acc[4][4][4];
    #pragma unroll
    for (int i = 0; i < 4; i++)
        #pragma unroll
        for (int j = 0; j < 4; j++)
            #pragma unroll
            for (int r = 0; r < 4; r++) acc[i][j][r] = 0.f;

    uint32_t ah_base = smem_u32(Ah), al_base = smem_u32(Al);
    uint32_t bh_base = smem_u32(Bh), bl_base = smem_u32(Bl);

    // per-lane ldmatrix address components
    int a_row = wm + (lane & 15);            // + mt*16
    int a_col = (lane >> 4) << 3;            // + ks
    int b_row = (lane & 7) + ((lane >> 3) & 1) * 8;   // + ks
    int b_col = wn + ((lane >> 4) << 3);     // + nt16*16

    for (int c = 0; c < nk; c++) {
        int k0 = c * 32;
        // ---- load + convert A chunk: 128 x 32 fp32 (4 float4 per thread)
        #pragma unroll
        for (int t = 0; t < 4; t++) {
            int f4 = tid + t * 256;              // 0..1023
            int row = f4 >> 3;
            int col = (f4 & 7) * 4;
            float4 v = *(const float4*)(A + (size_t)(m0 + row) * Kd + k0 + col);
            if (LN) {
                float mean = stat[(m0 + row) * 2];
                float rstd = stat[(m0 + row) * 2 + 1];
                v.x = (v.x - mean) * rstd * __ldg(gam + k0 + col + 0) + __ldg(bet + k0 + col + 0);
                v.y = (v.y - mean) * rstd * __ldg(gam + k0 + col + 1) + __ldg(bet + k0 + col + 1);
                v.z = (v.z - mean) * rstd * __ldg(gam + k0 + col + 2) + __ldg(bet + k0 + col + 2);
                v.w = (v.w - mean) * rstd * __ldg(gam + k0 + col + 3) + __ldg(bet + k0 + col + 3);
            }
            __nv_bfloat16 h0,h1,h2,h3,l0,l1,l2,l3;
            cvt_hilo(v.x,h0,l0); cvt_hilo(v.y,h1,l1);
            cvt_hilo(v.z,h2,l2); cvt_hilo(v.w,h3,l3);
            *(__nv_bfloat162*)&Ah[row*AST + col    ] = __nv_bfloat162(h0,h1);
            *(__nv_bfloat162*)&Ah[row*AST + col + 2] = __nv_bfloat162(h2,h3);
            *(__nv_bfloat162*)&Al[row*AST + col    ] = __nv_bfloat162(l0,l1);
            *(__nv_bfloat162*)&Al[row*AST + col + 2] = __nv_bfloat162(l2,l3);
        }
        // ---- load + convert B chunk: 32 x 128 fp32
        #pragma unroll
        for (int t = 0; t < 4; t++) {
            int f4 = tid + t * 256;
            int kr = f4 >> 5;
            int nn = (f4 & 31) * 4;
            float4 v = *(const float4*)(B + (size_t)(k0 + kr) * Nd + n0 + nn);
            __nv_bfloat16 h0,h1,h2,h3,l0,l1,l2,l3;
            cvt_hilo(v.x,h0,l0); cvt_hilo(v.y,h1,l1);
            cvt_hilo(v.z,h2,l2); cvt_hilo(v.w,h3,l3);
            *(__nv_bfloat162*)&Bh[kr*BST + nn    ] = __nv_bfloat162(h0,h1);
            *(__nv_bfloat162*)&Bh[kr*BST + nn + 2] = __nv_bfloat162(h2,h3);
            *(__nv_bfloat162*)&Bl[kr*BST + nn    ] = __nv_bfloat162(l0,l1);
            *(__nv_bfloat162*)&Bl[kr*BST + nn + 2] = __nv_bfloat162(l2,l3);
        }
        __syncthreads();

        // ---- three passes: (Ah,Bh), (Al,Bh), (Ah,Bl)
        #pragma unroll
        for (int pass = 0; pass < 3; pass++) {
            uint32_t abase = (pass == 1) ? al_base : ah_base;
            uint32_t bbase = (pass == 2) ? bl_base : bh_base;
            #pragma unroll
            for (int ks = 0; ks < 32; ks += 16) {
                uint32_t af[4][4];
                #pragma unroll
                for (int mt = 0; mt < 4; mt++) {
                    uint32_t addr = abase +
                        (uint32_t)(((a_row + mt*16) * AST + ks + a_col) * 2);
                    ldsm4(af[mt][0], af[mt][1], af[mt][2], af[mt][3], addr);
                }
                uint32_t bf[4][2];
                #pragma unroll
                for (int nt16 = 0; nt16 < 2; nt16++) {
                    uint32_t addr = bbase +
                        (uint32_t)(((ks + b_row) * BST + b_col + nt16*16) * 2);
                    ldsm4t(bf[nt16*2][0], bf[nt16*2][1],
                           bf[nt16*2+1][0], bf[nt16*2+1][1], addr);
                }
                #pragma unroll
                for (int mt = 0; mt < 4; mt++)
                    #pragma unroll
                    for (int nt = 0; nt < 4; nt++)
                        mma16816(acc[mt][nt], af[mt], bf[nt]);
            }
        }
        __syncthreads();
    }

    // ---- epilogue: direct stores (float2 per fragment half)
    int er = lane >> 2;
    int ec = (lane & 3) * 2;
    #pragma unroll
    for (int mt = 0; mt < 4; mt++) {
        #pragma unroll
        for (int nt = 0; nt < 4; nt++) {
            int row = m0 + wm + mt*16 + er;
            int col = n0 + wn + nt*8 + ec;
            *(float2*)(C + (size_t)row * Nd + col) =
                make_float2(acc[mt][nt][0], acc[mt][nt][1]);
            *(float2*)(C + (size_t)(row + 8) * Nd + col) =
                make_float2(acc[mt][nt][2], acc[mt][nt][3]);
        }
    }
}

// ---------------- z row stats (warp per edge row of 128) ----------------
__global__ __launch_bounds__(256) void k_zstats(const float* __restrict__ z) {
    int row  = blockIdx.x * 8 + (threadIdx.x >> 5);
    int lane = threadIdx.x & 31;
    float4 v = *(const float4*)(z + (size_t)row * CZ + lane * 4);
    float s  = v.x + v.y + v.z + v.w;
    float ss = v.x*v.x + v.y*v.y + v.z*v.z + v.w*v.w;
    #pragma unroll
    for (int o = 16; o; o >>= 1) {
        s  += __shfl_xor_sync(0xffffffffu, s,  o);
        ss += __shfl_xor_sync(0xffffffffu, ss, o);
    }
    if (lane == 0) {
        float mean = s * (1.0f / CZ);
        float var  = ss * (1.0f / CZ) - mean * mean;
        g_zstat[row*2    ] = mean;
        g_zstat[row*2 + 1] = rsqrtf(var + 1e-5f);
    }
}

// ---------------- z GEMM with LN fused into A-load ----------------
extern __shared__ float zsm[];
__global__ __launch_bounds__(256) void k_zgemm(const float* __restrict__ z,
                                               const float* __restrict__ zsc,
                                               const float* __restrict__ zbi) {
    float* As = zsm;                 // [128][129]
    float* Ws = zsm + 128 * 129;     // [128][44]
    int tid = threadIdx.x;
    int r0  = blockIdx.x * 128;

    for (int i = tid; i < CZ * EOC; i += 256) Ws[i] = g_wz[i];
    #pragma unroll
    for (int t = 0; t < 16; t++) {
        int flat = (tid + t * 256) * 4;
        int row  = flat >> 7;
        int col  = flat & 127;
        float mean = g_zstat[(size_t)(r0 + row) * 2];
        float rstd = g_zstat[(size_t)(r0 + row) * 2 + 1];
        float4 v = *(const float4*)(z + (size_t)(r0 + row) * CZ + col);
        As[row*129 + col + 0] = (v.x - mean) * rstd * zsc[col + 0] + zbi[col + 0];
        As[row*129 + col + 1] = (v.y - mean) * rstd * zsc[col + 1] + zbi[col + 1];
        As[row*129 + col + 2] = (v.z - mean) * rstd * zsc[col + 2] + zbi[col + 2];
        As[row*129 + col + 3] = (v.w - mean) * rstd * zsc[col + 3] + zbi[col + 3];
    }
    __syncthreads();

    int rA = tid >> 2;
    int rB = rA + 64;
    int c0 = (tid & 3) * 11;
    float acc0[11], acc1[11];
    #pragma unroll
    for (int j = 0; j < 11; j++) { acc0[j] = 0.f; acc1[j] = 0.f; }
    #pragma unroll 8
    for (int kk = 0; kk < CZ; kk++) {
        float a0 = As[rA*129 + kk];
        float a1 = As[rB*129 + kk];
        #pragma unroll
        for (int j = 0; j < 11; j++) {
            float w = Ws[kk*EOC + c0 + j];
            acc0[j] += a0 * w;
            acc1[j] += a1 * w;
        }
    }
    #pragma unroll
    for (int j = 0; j < 11; j++) {
        g_eo[(size_t)(r0 + rA) * EOC + c0 + j] = acc0[j];
        g_eo[(size_t)(r0 + rB) * EOC + c0 + j] = acc1[j];
    }
}

// ---------------- attention: one block (128 thr) per node ----------------
// rot/trans cancel algebraically (orthonormal rot, softmax sums to 1).
__global__ __launch_bounds__(128) void k_attn(const int*   __restrict__ edge_index,
                                              const float* __restrict__ s_mask,
                                              const float* __restrict__ head_w) {
    int node = blockIdx.x;
    int tid  = threadIdx.x;
    int b    = node >> 10;

    __shared__ int   nbroff_sh[KNB];
    __shared__ float msk_sh[KNB];
    __shared__ float q_sh[HH * CH];
    __shared__ float qp_sh[HH * PQn * 3];
    __shared__ float a_sh[HH][KNB];
    __shared__ float opt_sh[HH * PVn * 3];
    __shared__ float hw_sh[HH];

    if (tid < KNB) {
        int idx = edge_index[(size_t)node * KNB + tid];
        nbroff_sh[tid] = (b * NN + idx) * PROJ;
        msk_sh[tid]    = s_mask[node] * s_mask[b * NN + idx];
    }
    for (int i = tid; i < HH * CH; i += 128)
        q_sh[i] = g_proj[(size_t)node * PROJ + i];
    for (int i = tid; i < HH * PQn * 3; i += 128)
        qp_sh[i] = g_proj[(size_t)node * PROJ + 576 + i];
    if (tid < HH)
        hw_sh[tid] = log1pf(__expf(head_w[tid])) * 0.13608276348795434f;
    __syncthreads();

    int lane = tid & 31, warp = tid >> 5;
    int no   = nbroff_sh[lane];
    float mk = msk_sh[lane];
    const float* kr = g_proj + no;

    #pragma unroll
    for (int hi = 0; hi < 3; hi++) {
        int h = warp * 3 + hi;
        const float4* q4 = (const float4*)(q_sh + h * CH);
        const float4* k4 = (const float4*)(kr + 192 + h * CH);
        float dot = 0.f;
        #pragma unroll
        for (int c = 0; c < 4; c++) {
            float4 qa = q4[c], kb = k4[c];
            dot += qa.x*kb.x + qa.y*kb.y + qa.z*kb.z + qa.w*kb.w;
        }
        float sq = 0.f;
        const float* qp = qp_sh + h * 12;
        const float* kp = kr + 720 + h * 36;
        #pragma unroll
        for (int j = 0; j < 12; j++) {
            float d = qp[j] - kp[j];
            sq += d * d;
        }
        float bias  = g_eo[(size_t)(node * KNB + lane) * EOC + h];
        float logit = dot * 0.14433756729740643f
                    + bias * 0.5773502691896258f
                    - 0.5f * hw_sh[h] * sq
                    + 100000.0f * (mk - 1.0f);
        float mx = logit;
        #pragma unroll
        for (int o = 16; o; o >>= 1) mx = fmaxf(mx, __shfl_xor_sync(0xffffffffu, mx, o));
        float e = __expf(logit - mx);
        float sm = e;
        #pragma unroll
        for (int o = 16; o; o >>= 1) sm += __shfl_xor_sync(0xffffffffu, sm, o);
        a_sh[h][lane] = e / sm;
    }
    __syncthreads();

    float* cv = g_cvec + (size_t)node * CVC;
    for (int oi = tid; oi < CVC; oi += 128) {
        float acc = 0.f;
        if (oi < 192) {
            int h = oi >> 4;
            int off = 384 + oi;
            #pragma unroll 8
            for (int k = 0; k < KNB; k++)
                acc += a_sh[h][k] * g_proj[nbroff_sh[k] + off];
            cv[oi] = acc;
        } else if (oi < 480) {
            int j = oi - 192;
            int h = j / 24, r = j % 24;
            int off = 720 + h * 36 + 12 + r;
            #pragma unroll 8
            for (int k = 0; k < KNB; k++)
                acc += a_sh[h][k] * g_proj[nbroff_sh[k] + off];
            opt_sh[j] = acc;
            cv[oi] = acc;
        } else if (oi >= 576) {
            int j = oi - 576;
            int h = j >> 5, c = j & 31;
            const float* eb = g_eo + (size_t)(node * KNB) * EOC + 12 + c;
            #pragma unroll 8
            for (int k = 0; k < KNB; k++)
                acc += a_sh[h][k] * eb[(size_t)k * EOC];
            cv[oi] = acc;
        }
    }
    __syncthreads();
    if (tid < HH * PVn) {
        float x = opt_sh[tid*3], y = opt_sh[tid*3+1], zz = opt_sh[tid*3+2];
        cv[480 + tid] = sqrtf(x*x + y*y + zz*zz + 1e-8f);
    }
}

// ---------------- launch ----------------
extern "C" void kernel_launch(void* const* d_in, const int* in_sizes, int n_in,
                              void* d_out, int out_size) {
    const float* s           = (const float*)d_in[0];
    const float* z           = (const float*)d_in[1];
    const int*   edge_index  = (const int*)  d_in[2];
    // d_in[3] rot, d_in[4] trans: cancel algebraically -> unused
    const float* s_mask      = (const float*)d_in[5];
    const float* ln_s_scale  = (const float*)d_in[6];
    const float* ln_s_bias   = (const float*)d_in[7];
    const float* ln_z_scale  = (const float*)d_in[8];
    const float* ln_z_bias   = (const float*)d_in[9];
    const float* w_q         = (const float*)d_in[10];
    const float* w_k         = (const float*)d_in[11];
    const float* w_v         = (const float*)d_in[12];
    const float* w_q_pts     = (const float*)d_in[13];
    const float* w_kv_pts    = (const float*)d_in[14];
    const float* w_b         = (const float*)d_in[15];
    const float* w_down_z    = (const float*)d_in[16];
    const float* head_weights= (const float*)d_in[17];
    const float* w_out       = (const float*)d_in[18];
    float* out = (float*)d_out;

    cudaFuncSetAttribute(k_zgemm, cudaFuncAttributeMaxDynamicSharedMemorySize, 92160);

    void *p_wcat, *p_proj, *p_stat, *p_cvec;
    cudaGetSymbolAddress(&p_wcat, g_wcat);
    cudaGetSymbolAddress(&p_proj, g_proj);
    cudaGetSymbolAddress(&p_stat, g_stat);
    cudaGetSymbolAddress(&p_cvec, g_cvec);

    pack_wcat<<<(CS * PROJ + 255) / 256, 256>>>(w_q, w_k, w_v, w_q_pts, w_kv_pts);
    pack_wz  <<<(CZ * EOC  + 255) / 256, 256>>>(w_b, w_down_z);
    k_stat_s <<<NODES / 8, 256>>>(s);

    // GEMM1: LN(s) @ wcat -> proj   (4096x384)@(384x1152), bf16x3 mma.sync
    tgemm<true><<<dim3(NODES/128, PROJ/128), 256>>>(
        s, (const float*)p_wcat, (float*)p_proj, CS, PROJ, CS/32,
        (const float*)p_stat, ln_s_scale, ln_s_bias);

    // z path
    k_zstats<<<EDGES / 8, 256>>>(z);
    k_zgemm <<<EDGES / 128, 256, (128 * 129 + CZ * EOC) * sizeof(float)>>>(
        z, ln_z_scale, ln_z_bias);

    k_attn<<<NODES, 128>>>(edge_index, s_mask, head_weights);

    // GEMM2: cvec @ w_out -> out    (4096x960)@(960x384), bf16x3 mma.sync
    tgemm<false><<<dim3(NODES/128, COUT/128), 256>>>(
        (const float*)p_cvec, w_out, out, CVC, COUT, CVC/32,
        nullptr, nullptr, nullptr);
}